// round 1
// baseline (speedup 1.0000x reference)
#include <cuda_runtime.h>
#include <stdint.h>
#include <math.h>

// Problem constants (shapes fixed by the dataset)
#define NMAX 50000
#define EMAX 800000

// ---------------- scratch (static __device__ — no allocation) ----------------
__device__ float g_z[(size_t)NMAX * 128];      // per-head projections [N, H*O]
__device__ float g_el[(size_t)NMAX * 8];       // a_l . z  [N,H]
__device__ float g_er[(size_t)NMAX * 8];       // a_r . z  [N,H]
__device__ float g_h[(size_t)NMAX * 128];      // elu(gat)+x  [N,D]
__device__ float g_lnv[(size_t)NMAX * 128];    // layernorm(h)
__device__ float g_inter[(size_t)NMAX * 512];  // gelu(ln@w1+b1)
__device__ int   g_cnt[NMAX];
__device__ int   g_off[NMAX + 1];
__device__ int   g_cur[NMAX];
__device__ int   g_csrc[EMAX];                 // src node per dst-sorted edge slot

// ---------------- f32x2 packed-FMA helpers (SASS FFMA2) ----------------
__device__ __forceinline__ unsigned long long pack2(float x) {
    unsigned long long r;
    unsigned xi = __float_as_uint(x);
    asm("mov.b64 %0, {%1, %1};" : "=l"(r) : "r"(xi));
    return r;
}
__device__ __forceinline__ void fma2(unsigned long long& acc,
                                     unsigned long long a, unsigned long long b) {
    asm("fma.rn.f32x2 %0, %1, %2, %0;" : "+l"(acc) : "l"(a), "l"(b));
}
__device__ __forceinline__ float2 unpack2(unsigned long long v) {
    unsigned lo, hi;
    asm("mov.b64 {%0, %1}, %2;" : "=r"(lo), "=r"(hi) : "l"(v));
    return make_float2(__uint_as_float(lo), __uint_as_float(hi));
}

__device__ __forceinline__ float gelu_exact(float v) {
    return 0.5f * v * (1.0f + erff(v * 0.70710678118654752440f));
}

// =====================================================================
// K1: z = x @ W  (W[d][h*16+o] = fc_w[h][d][o]),  plus el/er epilogue
// BM=64, BN=128 (full), BK=32, 256 threads, 32 outputs/thread via f32x2
// =====================================================================
__global__ __launch_bounds__(256) void proj_kernel(
    const float* __restrict__ x, const float* __restrict__ fcw,
    const float* __restrict__ a_l, const float* __restrict__ a_r, int M)
{
    constexpr int BM = 64, BK = 32;
    __shared__ float As[BM][BK + 1];
    __shared__ float Bs[BK * 128];

    int t = threadIdx.x;
    int r = t >> 2, g = t & 3;
    int row0 = blockIdx.x * BM;

    unsigned long long acc[16];
#pragma unroll
    for (int i = 0; i < 16; i++) acc[i] = 0ull;

    const float4* x4 = (const float4*)x;
    const float4* w4 = (const float4*)fcw;

    for (int k0 = 0; k0 < 128; k0 += BK) {
#pragma unroll
        for (int i = 0; i < 2; i++) {
            int idx = t + i * 256;           // 64 rows x 8 float4
            int ar = idx >> 3, ac4 = idx & 7;
            int grow = row0 + ar;
            float4 v = make_float4(0.f, 0.f, 0.f, 0.f);
            if (grow < M) v = x4[grow * 32 + (k0 >> 2) + ac4];
            As[ar][ac4 * 4 + 0] = v.x; As[ar][ac4 * 4 + 1] = v.y;
            As[ar][ac4 * 4 + 2] = v.z; As[ar][ac4 * 4 + 3] = v.w;
        }
#pragma unroll
        for (int i = 0; i < 4; i++) {
            int idx = t + i * 256;           // 32 rows x 32 float4
            int br = idx >> 5, bc4 = idx & 31;
            int h = bc4 >> 2, o4 = bc4 & 3;
            float4 v = w4[h * 512 + (k0 + br) * 4 + o4];  // fc_w[h][k0+br][4*o4..]
            ((float4*)Bs)[br * 32 + bc4] = v;
        }
        __syncthreads();
#pragma unroll
        for (int kk = 0; kk < BK; kk++) {
            unsigned long long xx = pack2(As[r][kk]);
            const ulonglong2* bp = (const ulonglong2*)(Bs + kk * 128 + g * 32);
#pragma unroll
            for (int j = 0; j < 8; j++) {
                ulonglong2 bb = bp[j];
                fma2(acc[2 * j],     xx, bb.x);
                fma2(acc[2 * j + 1], xx, bb.y);
            }
        }
        __syncthreads();
    }

    int grow = row0 + r;
    if (grow >= M) return;

    float accf[32];
#pragma unroll
    for (int i = 0; i < 16; i++) { float2 f = unpack2(acc[i]); accf[2 * i] = f.x; accf[2 * i + 1] = f.y; }

    float4* z4 = (float4*)g_z;
#pragma unroll
    for (int j = 0; j < 8; j++)
        z4[grow * 32 + g * 8 + j] =
            make_float4(accf[4 * j], accf[4 * j + 1], accf[4 * j + 2], accf[4 * j + 3]);

#pragma unroll
    for (int hh = 0; hh < 2; hh++) {
        int head = 2 * g + hh;
        float sl = 0.f, sr = 0.f;
#pragma unroll
        for (int o = 0; o < 16; o++) {
            float v = accf[hh * 16 + o];
            sl += v * a_l[head * 16 + o];
            sr += v * a_r[head * 16 + o];
        }
        g_el[grow * 8 + head] = sl;
        g_er[grow * 8 + head] = sr;
    }
}

// =====================================================================
// K2: CSR build (count -> scan -> scatter)
// =====================================================================
__global__ void zero_cnt_kernel(int n) {
    int i = blockIdx.x * blockDim.x + threadIdx.x;
    if (i < n) g_cnt[i] = 0;
}

__global__ void hist_kernel(const int* __restrict__ dst, int E) {
    int i = blockIdx.x * blockDim.x + threadIdx.x;
    if (i < E) atomicAdd(&g_cnt[dst[i]], 1);
}

__global__ void scan_kernel(int n) {
    __shared__ int partial[1024];
    int t = threadIdx.x;
    int chunk = (n + 1023) / 1024;
    int begin = t * chunk;
    int end = begin + chunk; if (end > n) end = n;
    int s = 0;
    for (int i = begin; i < end; i++) s += g_cnt[i];
    partial[t] = s;
    __syncthreads();
    for (int d2 = 1; d2 < 1024; d2 <<= 1) {
        int v = (t >= d2) ? partial[t - d2] : 0;
        __syncthreads();
        partial[t] += v;
        __syncthreads();
    }
    int run = (t == 0) ? 0 : partial[t - 1];
    for (int i = begin; i < end; i++) {
        g_off[i] = run;
        g_cur[i] = run;
        run += g_cnt[i];
    }
    if (t == 1023) g_off[n] = partial[1023];
}

__global__ void scatter_kernel(const int* __restrict__ src, const int* __restrict__ dst, int E) {
    int i = blockIdx.x * blockDim.x + threadIdx.x;
    if (i < E) {
        int d = dst[i];
        int p = atomicAdd(&g_cur[d], 1);
        g_csrc[p] = src[i];
    }
}

// =====================================================================
// K3: per-dst edge softmax + weighted aggregation + elu + residual
// One warp per dst node. Loop1: denom (4 edges x 8 heads per step).
// Loop2: lane owns 4 output dims (one head), accumulates alpha*z[src].
// =====================================================================
__global__ __launch_bounds__(256) void gat_kernel(const float* __restrict__ x, int n)
{
    int warp = (blockIdx.x * blockDim.x + threadIdx.x) >> 5;
    int lane = threadIdx.x & 31;
    if (warp >= n) return;
    int d = warp;
    int beg = g_off[d], end = g_off[d + 1];

    int h1 = lane & 7, eo = lane >> 3;
    float er_a = g_er[d * 8 + h1];

    // pass 1: denominator per head
    float denom = 0.f;
    int iters = (end - beg + 3) >> 2;
    for (int it = 0; it < iters; it++) {
        int idx = beg + it * 4 + eo;
        float ex = 0.f;
        if (idx < end) {
            int s = g_csrc[idx];
            float e = g_el[s * 8 + h1] + er_a;
            e = (e > 0.f) ? e : 0.01f * e;
            ex = __expf(e);
        }
        denom += ex;
    }
    denom += __shfl_xor_sync(0xffffffffu, denom, 8);
    denom += __shfl_xor_sync(0xffffffffu, denom, 16);

    int h2 = lane >> 2;  // head owned in pass 2
    float dh = __shfl_sync(0xffffffffu, denom, h2);
    float er_b = __shfl_sync(0xffffffffu, er_a, h2);
    float rd = (dh > 0.f) ? (1.0f / dh) : 0.f;

    // pass 2: weighted aggregation (each lane: 4 contiguous dims within head h2)
    float4 acc = make_float4(0.f, 0.f, 0.f, 0.f);
    const float4* z4 = (const float4*)g_z;
    for (int i = beg; i < end; i++) {
        int s = g_csrc[i];
        float e = g_el[s * 8 + h2] + er_b;
        e = (e > 0.f) ? e : 0.01f * e;
        float alpha = __expf(e) * rd;
        float4 zv = z4[s * 32 + lane];
        acc.x += alpha * zv.x;
        acc.y += alpha * zv.y;
        acc.z += alpha * zv.z;
        acc.w += alpha * zv.w;
    }

    // elu + residual with x
    float4 xr = ((const float4*)x)[d * 32 + lane];
    acc.x = ((acc.x > 0.f) ? acc.x : (__expf(acc.x) - 1.f)) + xr.x;
    acc.y = ((acc.y > 0.f) ? acc.y : (__expf(acc.y) - 1.f)) + xr.y;
    acc.z = ((acc.z > 0.f) ? acc.z : (__expf(acc.z) - 1.f)) + xr.z;
    acc.w = ((acc.w > 0.f) ? acc.w : (__expf(acc.w) - 1.f)) + xr.w;
    ((float4*)g_h)[d * 32 + lane] = acc;
}

// =====================================================================
// K4: LayerNorm (one warp per row, float4 per lane)
// =====================================================================
__global__ __launch_bounds__(256) void ln_kernel(
    const float* __restrict__ gg, const float* __restrict__ bb, int n)
{
    int warp = (blockIdx.x * blockDim.x + threadIdx.x) >> 5;
    int lane = threadIdx.x & 31;
    if (warp >= n) return;
    float4 v = ((const float4*)g_h)[warp * 32 + lane];
    float s = v.x + v.y + v.z + v.w;
#pragma unroll
    for (int o = 16; o; o >>= 1) s += __shfl_xor_sync(0xffffffffu, s, o);
    float mu = s * (1.f / 128.f);
    float dx = v.x - mu, dy = v.y - mu, dz = v.z - mu, dw = v.w - mu;
    float q = dx * dx + dy * dy + dz * dz + dw * dw;
#pragma unroll
    for (int o = 16; o; o >>= 1) q += __shfl_xor_sync(0xffffffffu, q, o);
    float rs = rsqrtf(q * (1.f / 128.f) + 1e-6f);
    float4 g4 = ((const float4*)gg)[lane];
    float4 b4 = ((const float4*)bb)[lane];
    float4 o4 = make_float4(dx * rs * g4.x + b4.x, dy * rs * g4.y + b4.y,
                            dz * rs * g4.z + b4.z, dw * rs * g4.w + b4.w);
    ((float4*)g_lnv)[warp * 32 + lane] = o4;
}

// =====================================================================
// K5: inter = gelu(ln @ w1 + b1)   [N,128]x[128,512]
// =====================================================================
__global__ __launch_bounds__(256) void ffn1_kernel(
    const float* __restrict__ w1, const float* __restrict__ b1, int M)
{
    constexpr int BM = 64, BK = 32;
    __shared__ float As[BM][BK + 1];
    __shared__ float Bs[BK * 128];

    int t = threadIdx.x;
    int r = t >> 2, g = t & 3;
    int row0 = blockIdx.x * BM;
    int col0 = blockIdx.y * 128;

    unsigned long long acc[16];
#pragma unroll
    for (int i = 0; i < 16; i++) acc[i] = 0ull;

    const float4* A4 = (const float4*)g_lnv;
    const float4* B4 = (const float4*)w1;

    for (int k0 = 0; k0 < 128; k0 += BK) {
#pragma unroll
        for (int i = 0; i < 2; i++) {
            int idx = t + i * 256;
            int ar = idx >> 3, ac4 = idx & 7;
            int grow = row0 + ar;
            float4 v = make_float4(0.f, 0.f, 0.f, 0.f);
            if (grow < M) v = A4[grow * 32 + (k0 >> 2) + ac4];
            As[ar][ac4 * 4 + 0] = v.x; As[ar][ac4 * 4 + 1] = v.y;
            As[ar][ac4 * 4 + 2] = v.z; As[ar][ac4 * 4 + 3] = v.w;
        }
#pragma unroll
        for (int i = 0; i < 4; i++) {
            int idx = t + i * 256;
            int br = idx >> 5, bc4 = idx & 31;
            float4 v = B4[(k0 + br) * 128 + (col0 >> 2) + bc4];
            ((float4*)Bs)[br * 32 + bc4] = v;
        }
        __syncthreads();
#pragma unroll
        for (int kk = 0; kk < BK; kk++) {
            unsigned long long xx = pack2(As[r][kk]);
            const ulonglong2* bp = (const ulonglong2*)(Bs + kk * 128 + g * 32);
#pragma unroll
            for (int j = 0; j < 8; j++) {
                ulonglong2 bv = bp[j];
                fma2(acc[2 * j],     xx, bv.x);
                fma2(acc[2 * j + 1], xx, bv.y);
            }
        }
        __syncthreads();
    }

    int grow = row0 + r;
    if (grow >= M) return;
    float accf[32];
#pragma unroll
    for (int i = 0; i < 16; i++) { float2 f = unpack2(acc[i]); accf[2 * i] = f.x; accf[2 * i + 1] = f.y; }

    float4* out4 = (float4*)g_inter;
#pragma unroll
    for (int j = 0; j < 8; j++) {
        int c4 = (col0 >> 2) + g * 8 + j;
        float4 bv = ((const float4*)b1)[c4];
        float4 v;
        v.x = gelu_exact(accf[4 * j + 0] + bv.x);
        v.y = gelu_exact(accf[4 * j + 1] + bv.y);
        v.z = gelu_exact(accf[4 * j + 2] + bv.z);
        v.w = gelu_exact(accf[4 * j + 3] + bv.w);
        out4[grow * 128 + c4] = v;
    }
}

// =====================================================================
// K6: out = inter @ w2 + b2 + h   [N,512]x[512,128]
// =====================================================================
__global__ __launch_bounds__(256) void ffn2_kernel(
    const float* __restrict__ w2, const float* __restrict__ b2,
    float* __restrict__ out, int M)
{
    constexpr int BM = 64, BK = 32;
    __shared__ float As[BM][BK + 1];
    __shared__ float Bs[BK * 128];

    int t = threadIdx.x;
    int r = t >> 2, g = t & 3;
    int row0 = blockIdx.x * BM;

    unsigned long long acc[16];
#pragma unroll
    for (int i = 0; i < 16; i++) acc[i] = 0ull;

    const float4* A4 = (const float4*)g_inter;
    const float4* B4 = (const float4*)w2;

    for (int k0 = 0; k0 < 512; k0 += BK) {
#pragma unroll
        for (int i = 0; i < 2; i++) {
            int idx = t + i * 256;
            int ar = idx >> 3, ac4 = idx & 7;
            int grow = row0 + ar;
            float4 v = make_float4(0.f, 0.f, 0.f, 0.f);
            if (grow < M) v = A4[grow * 128 + (k0 >> 2) + ac4];
            As[ar][ac4 * 4 + 0] = v.x; As[ar][ac4 * 4 + 1] = v.y;
            As[ar][ac4 * 4 + 2] = v.z; As[ar][ac4 * 4 + 3] = v.w;
        }
#pragma unroll
        for (int i = 0; i < 4; i++) {
            int idx = t + i * 256;
            int br = idx >> 5, bc4 = idx & 31;
            float4 v = B4[(k0 + br) * 32 + bc4];
            ((float4*)Bs)[br * 32 + bc4] = v;
        }
        __syncthreads();
#pragma unroll
        for (int kk = 0; kk < BK; kk++) {
            unsigned long long xx = pack2(As[r][kk]);
            const ulonglong2* bp = (const ulonglong2*)(Bs + kk * 128 + g * 32);
#pragma unroll
            for (int j = 0; j < 8; j++) {
                ulonglong2 bv = bp[j];
                fma2(acc[2 * j],     xx, bv.x);
                fma2(acc[2 * j + 1], xx, bv.y);
            }
        }
        __syncthreads();
    }

    int grow = row0 + r;
    if (grow >= M) return;
    float accf[32];
#pragma unroll
    for (int i = 0; i < 16; i++) { float2 f = unpack2(acc[i]); accf[2 * i] = f.x; accf[2 * i + 1] = f.y; }

    float4* out4 = (float4*)out;
#pragma unroll
    for (int j = 0; j < 8; j++) {
        int c4 = g * 8 + j;
        float4 bv = ((const float4*)b2)[c4];
        float4 hv = ((const float4*)g_h)[grow * 32 + c4];
        float4 v;
        v.x = accf[4 * j + 0] + bv.x + hv.x;
        v.y = accf[4 * j + 1] + bv.y + hv.y;
        v.z = accf[4 * j + 2] + bv.z + hv.z;
        v.w = accf[4 * j + 3] + bv.w + hv.w;
        out4[grow * 32 + c4] = v;
    }
}

// =====================================================================
extern "C" void kernel_launch(void* const* d_in, const int* in_sizes, int n_in,
                              void* d_out, int out_size)
{
    const float* x    = (const float*)d_in[0];
    const float* fcw  = (const float*)d_in[1];
    const float* a_l  = (const float*)d_in[2];
    const float* a_r  = (const float*)d_in[3];
    const float* ln_g = (const float*)d_in[4];
    const float* ln_b = (const float*)d_in[5];
    const float* w1   = (const float*)d_in[6];
    const float* b1   = (const float*)d_in[7];
    const float* w2   = (const float*)d_in[8];
    const float* b2   = (const float*)d_in[9];
    const int*   src  = (const int*)d_in[10];
    const int*   dst  = (const int*)d_in[11];

    int n = in_sizes[0] / 128;   // 50000
    int E = in_sizes[10];        // 800000

    // CSR build + projection (independent; serialized on default stream)
    zero_cnt_kernel<<<(n + 255) / 256, 256>>>(n);
    hist_kernel<<<(E + 255) / 256, 256>>>(dst, E);
    proj_kernel<<<(n + 63) / 64, 256>>>(x, fcw, a_l, a_r, n);
    scan_kernel<<<1, 1024>>>(n);
    scatter_kernel<<<(E + 255) / 256, 256>>>(src, dst, E);

    // GAT aggregation + elu + residual
    gat_kernel<<<(n + 7) / 8, 256>>>(x, n);

    // FFN
    ln_kernel<<<(n + 7) / 8, 256>>>(ln_g, ln_b, n);
    ffn1_kernel<<<dim3((n + 63) / 64, 4), 256>>>(w1, b1, n);
    ffn2_kernel<<<dim3((n + 63) / 64, 1), 256>>>(w2, b2, (float*)d_out, n);
}

// round 2
// speedup vs baseline: 7.0950x; 7.0950x over previous
#include <cuda_runtime.h>
#include <stdint.h>
#include <math.h>

#define NMAX 50000
#define EMAX 800000

// ---------------- scratch (static __device__ — no allocation) ----------------
__device__ float g_z[(size_t)NMAX * 128];      // per-head projections [N, H*O]
__device__ float g_el[(size_t)NMAX * 8];       // a_l . z  [N,H]
__device__ float g_er[(size_t)NMAX * 8];       // a_r . z  [N,H]
__device__ float g_h[(size_t)NMAX * 128];      // elu(gat)+x  [N,D]
__device__ float g_lnv[(size_t)NMAX * 128];    // layernorm(h)
__device__ float g_inter[(size_t)NMAX * 512];  // gelu(ln@w1+b1)
__device__ int   g_cnt[NMAX];
__device__ int   g_off[NMAX + 1];
__device__ int   g_cur[NMAX];
__device__ int   g_csrc[EMAX];

// ---------------- f32x2 packed-FMA helpers (SASS FFMA2) ----------------
__device__ __forceinline__ unsigned long long pack2(float x) {
    unsigned long long r;
    unsigned xi = __float_as_uint(x);
    asm("mov.b64 %0, {%1, %1};" : "=l"(r) : "r"(xi));
    return r;
}
__device__ __forceinline__ void fma2(unsigned long long& acc,
                                     unsigned long long a, unsigned long long b) {
    asm("fma.rn.f32x2 %0, %1, %2, %0;" : "+l"(acc) : "l"(a), "l"(b));
}
__device__ __forceinline__ float2 unpack2(unsigned long long v) {
    unsigned lo, hi;
    asm("mov.b64 {%0, %1}, %2;" : "=r"(lo), "=r"(hi) : "l"(v));
    return make_float2(__uint_as_float(lo), __uint_as_float(hi));
}
__device__ __forceinline__ float gelu_exact(float v) {
    return 0.5f * v * (1.0f + erff(v * 0.70710678118654752440f));
}

// =====================================================================
// Register-tiled GEMM: C[M,N] = A[M,KTOT] @ B[KTOT,N]
// BM=BN=128, BK=16, 256 threads (16x16), 8x8 outputs per thread
// (split 4+4 rows / 4+4 cols for conflict-free LDS.128).
// EPI: 0 = proj (B gathered from fc_w, out=g_z)
//      1 = ffn1 (gelu(acc+bias) -> g_inter, N=512)
//      2 = ffn2 (acc+bias+res -> out, N=128)
// =====================================================================
template<int KTOT, int EPI>
__global__ __launch_bounds__(256) void gemm_kernel(
    const float* __restrict__ A, const float* __restrict__ B,
    const float* __restrict__ bias, const float* __restrict__ res,
    float* __restrict__ out, int M)
{
    constexpr int NTOT = (EPI == 1) ? 512 : 128;
    __shared__ float As[16 * 132];   // k-major, stride 132 (16B aligned, conflict-spread)
    __shared__ float Bs[16 * 128];   // row-major [k][col]

    const int t  = threadIdx.x;
    const int tx = t & 15, ty = t >> 4;
    const int row0 = blockIdx.x * 128;
    const int col0 = blockIdx.y * 128;

    unsigned long long acc[8][4];
#pragma unroll
    for (int r = 0; r < 8; r++)
#pragma unroll
        for (int p = 0; p < 4; p++) acc[r][p] = 0ull;

    const float4* A4 = (const float4*)A;
    const float4* B4 = (const float4*)B;

#pragma unroll 1
    for (int k0 = 0; k0 < KTOT; k0 += 16) {
        // ---- load A tile [128 rows x 16 k], transposed to As[k][row] ----
#pragma unroll
        for (int i = 0; i < 2; i++) {
            int row = (t >> 2) + i * 64;
            int c4  = t & 3;
            int grow = row0 + row;
            float4 v = make_float4(0.f, 0.f, 0.f, 0.f);
            if (grow < M) v = A4[grow * (KTOT >> 2) + (k0 >> 2) + c4];
            As[(c4 * 4 + 0) * 132 + row] = v.x;
            As[(c4 * 4 + 1) * 132 + row] = v.y;
            As[(c4 * 4 + 2) * 132 + row] = v.z;
            As[(c4 * 4 + 3) * 132 + row] = v.w;
        }
        // ---- load B tile [16 k x 128 cols] ----
        if (EPI == 0) {
            // B[k][n] = fc_w[n>>4][k][n&15], fc_w strides (2048,16,1)
#pragma unroll
            for (int i = 0; i < 8; i++) {
                int idx = t + i * 256;
                int kk = idx >> 7, col = idx & 127;
                Bs[kk * 128 + col] = B[(col >> 4) * 2048 + (k0 + kk) * 16 + (col & 15)];
            }
        } else {
#pragma unroll
            for (int i = 0; i < 2; i++) {
                int kk = t >> 4;
                int c4 = (t & 15) + i * 16;
                float4 v = B4[(size_t)(k0 + kk) * (NTOT >> 2) + (col0 >> 2) + c4];
                ((float4*)Bs)[kk * 32 + c4] = v;
            }
        }
        __syncthreads();

#pragma unroll
        for (int kk = 0; kk < 16; kk++) {
            float4 a0 = *(const float4*)&As[kk * 132 + ty * 4];
            float4 a1 = *(const float4*)&As[kk * 132 + 64 + ty * 4];
            ulonglong2 b0 = *(const ulonglong2*)&Bs[kk * 128 + tx * 4];
            ulonglong2 b1 = *(const ulonglong2*)&Bs[kk * 128 + 64 + tx * 4];
            float av[8] = {a0.x, a0.y, a0.z, a0.w, a1.x, a1.y, a1.z, a1.w};
#pragma unroll
            for (int r = 0; r < 8; r++) {
                unsigned long long pa = pack2(av[r]);
                fma2(acc[r][0], pa, b0.x);
                fma2(acc[r][1], pa, b0.y);
                fma2(acc[r][2], pa, b1.x);
                fma2(acc[r][3], pa, b1.y);
            }
        }
        __syncthreads();
    }

    // ---- epilogue ----
#pragma unroll
    for (int r = 0; r < 8; r++) {
        int row = row0 + ((r < 4) ? (ty * 4 + r) : (64 + ty * 4 + r - 4));
        if (row >= M) continue;
#pragma unroll
        for (int p = 0; p < 4; p++) {
            float2 v = unpack2(acc[r][p]);
            int lcol = (p < 2) ? (tx * 4 + 2 * p) : (64 + tx * 4 + 2 * (p - 2));
            int col = col0 + lcol;
            if (EPI == 0) {
                *(float2*)&out[(size_t)row * 128 + col] = v;
            } else if (EPI == 1) {
                v.x = gelu_exact(v.x + bias[col]);
                v.y = gelu_exact(v.y + bias[col + 1]);
                *(float2*)&out[(size_t)row * 512 + col] = v;
            } else {
                v.x += bias[col] + res[(size_t)row * 128 + col];
                v.y += bias[col + 1] + res[(size_t)row * 128 + col + 1];
                *(float2*)&out[(size_t)row * 128 + col] = v;
            }
        }
    }
}

// =====================================================================
// el/er epilogue: warp per node. lane l covers dims l*4..l*4+3 (head l>>2).
// =====================================================================
__global__ __launch_bounds__(256) void eler_kernel(
    const float* __restrict__ a_l, const float* __restrict__ a_r, int n)
{
    int warp = (blockIdx.x * blockDim.x + threadIdx.x) >> 5;
    int lane = threadIdx.x & 31;
    if (warp >= n) return;
    float4 z = ((const float4*)g_z)[(size_t)warp * 32 + lane];
    float4 al = ((const float4*)a_l)[lane];
    float4 ar = ((const float4*)a_r)[lane];
    float sl = z.x * al.x + z.y * al.y + z.z * al.z + z.w * al.w;
    float sr = z.x * ar.x + z.y * ar.y + z.z * ar.z + z.w * ar.w;
    sl += __shfl_xor_sync(0xffffffffu, sl, 1);
    sl += __shfl_xor_sync(0xffffffffu, sl, 2);
    sr += __shfl_xor_sync(0xffffffffu, sr, 1);
    sr += __shfl_xor_sync(0xffffffffu, sr, 2);
    if ((lane & 3) == 0) {
        int head = lane >> 2;
        g_el[warp * 8 + head] = sl;
        g_er[warp * 8 + head] = sr;
    }
}

// =====================================================================
// CSR build
// =====================================================================
__global__ void zero_cnt_kernel(int n) {
    int i = blockIdx.x * blockDim.x + threadIdx.x;
    if (i < n) g_cnt[i] = 0;
}

__global__ void hist_kernel(const int* __restrict__ dst, int E) {
    int i = blockIdx.x * blockDim.x + threadIdx.x;
    if (i < E) atomicAdd(&g_cnt[dst[i]], 1);
}

__global__ __launch_bounds__(1024) void scan_kernel(int n) {
    int t = threadIdx.x;
    int chunk = (n + 1023) >> 10;
    int b = t * chunk;
    int e = b + chunk; if (e > n) e = n;
    int s = 0;
    for (int i = b; i < e; i++) s += g_cnt[i];
    int own = s;
    int lane = t & 31, w = t >> 5;
#pragma unroll
    for (int d = 1; d < 32; d <<= 1) {
        int v = __shfl_up_sync(0xffffffffu, s, d);
        if (lane >= d) s += v;
    }
    __shared__ int ws[32];
    if (lane == 31) ws[w] = s;
    __syncthreads();
    if (w == 0) {
        int v = ws[lane];
#pragma unroll
        for (int d = 1; d < 32; d <<= 1) {
            int u = __shfl_up_sync(0xffffffffu, v, d);
            if (lane >= d) v += u;
        }
        ws[lane] = v;
    }
    __syncthreads();
    int run = s - own + (w ? ws[w - 1] : 0);
    for (int i = b; i < e; i++) {
        g_off[i] = run;
        g_cur[i] = run;
        run += g_cnt[i];
    }
    if (t == 1023) g_off[n] = ws[31];
}

__global__ void scatter_kernel(const int* __restrict__ src, const int* __restrict__ dst, int E) {
    int i = blockIdx.x * blockDim.x + threadIdx.x;
    if (i < E) {
        int d = dst[i];
        int p = atomicAdd(&g_cur[d], 1);
        g_csrc[p] = src[i];
    }
}

// =====================================================================
// GAT: per-dst softmax + aggregation + elu + residual + fused LayerNorm
// One warp per dst node.
// =====================================================================
__global__ __launch_bounds__(256) void gat_ln_kernel(
    const float* __restrict__ x,
    const float* __restrict__ gg, const float* __restrict__ bb, int n)
{
    int warp = (blockIdx.x * blockDim.x + threadIdx.x) >> 5;
    int lane = threadIdx.x & 31;
    if (warp >= n) return;
    int d = warp;
    int beg = g_off[d], end = g_off[d + 1];

    int h1 = lane & 7, eo = lane >> 3;
    float er_a = g_er[d * 8 + h1];

    // pass 1: per-head denominator (4 edges x 8 heads per step)
    float denom = 0.f;
    int iters = (end - beg + 3) >> 2;
    for (int it = 0; it < iters; it++) {
        int idx = beg + it * 4 + eo;
        float ex = 0.f;
        if (idx < end) {
            int s = g_csrc[idx];
            float e = g_el[s * 8 + h1] + er_a;
            e = (e > 0.f) ? e : 0.01f * e;
            ex = __expf(e);
        }
        denom += ex;
    }
    denom += __shfl_xor_sync(0xffffffffu, denom, 8);
    denom += __shfl_xor_sync(0xffffffffu, denom, 16);

    int h2 = lane >> 2;
    float dh = __shfl_sync(0xffffffffu, denom, h2);
    float er_b = __shfl_sync(0xffffffffu, er_a, h2);
    float rd = (dh > 0.f) ? (1.0f / dh) : 0.f;

    // pass 2: weighted aggregation (lane owns 4 contiguous dims in head h2)
    float4 acc = make_float4(0.f, 0.f, 0.f, 0.f);
    const float4* z4 = (const float4*)g_z;
    for (int i = beg; i < end; i++) {
        int s = g_csrc[i];
        float e = g_el[s * 8 + h2] + er_b;
        e = (e > 0.f) ? e : 0.01f * e;
        float alpha = __expf(e) * rd;
        float4 zv = z4[(size_t)s * 32 + lane];
        acc.x += alpha * zv.x;
        acc.y += alpha * zv.y;
        acc.z += alpha * zv.z;
        acc.w += alpha * zv.w;
    }

    // elu + residual
    float4 xr = ((const float4*)x)[(size_t)d * 32 + lane];
    acc.x = ((acc.x > 0.f) ? acc.x : (__expf(acc.x) - 1.f)) + xr.x;
    acc.y = ((acc.y > 0.f) ? acc.y : (__expf(acc.y) - 1.f)) + xr.y;
    acc.z = ((acc.z > 0.f) ? acc.z : (__expf(acc.z) - 1.f)) + xr.z;
    acc.w = ((acc.w > 0.f) ? acc.w : (__expf(acc.w) - 1.f)) + xr.w;
    ((float4*)g_h)[(size_t)d * 32 + lane] = acc;

    // fused LayerNorm
    float s = acc.x + acc.y + acc.z + acc.w;
#pragma unroll
    for (int o = 16; o; o >>= 1) s += __shfl_xor_sync(0xffffffffu, s, o);
    float mu = s * (1.f / 128.f);
    float dx = acc.x - mu, dy = acc.y - mu, dz = acc.z - mu, dw = acc.w - mu;
    float q = dx * dx + dy * dy + dz * dz + dw * dw;
#pragma unroll
    for (int o = 16; o; o >>= 1) q += __shfl_xor_sync(0xffffffffu, q, o);
    float rs = rsqrtf(q * (1.f / 128.f) + 1e-6f);
    float4 g4 = ((const float4*)gg)[lane];
    float4 b4 = ((const float4*)bb)[lane];
    float4 o4 = make_float4(dx * rs * g4.x + b4.x, dy * rs * g4.y + b4.y,
                            dz * rs * g4.z + b4.z, dw * rs * g4.w + b4.w);
    ((float4*)g_lnv)[(size_t)d * 32 + lane] = o4;
}

// =====================================================================
extern "C" void kernel_launch(void* const* d_in, const int* in_sizes, int n_in,
                              void* d_out, int out_size)
{
    const float* x    = (const float*)d_in[0];
    const float* fcw  = (const float*)d_in[1];
    const float* a_l  = (const float*)d_in[2];
    const float* a_r  = (const float*)d_in[3];
    const float* ln_g = (const float*)d_in[4];
    const float* ln_b = (const float*)d_in[5];
    const float* w1   = (const float*)d_in[6];
    const float* b1   = (const float*)d_in[7];
    const float* w2   = (const float*)d_in[8];
    const float* b2   = (const float*)d_in[9];
    const int*   src  = (const int*)d_in[10];
    const int*   dst  = (const int*)d_in[11];

    int n = in_sizes[0] / 128;
    int E = in_sizes[10];

    float* g_z_p;     cudaGetSymbolAddress((void**)&g_z_p, g_z);
    float* g_lnv_p;   cudaGetSymbolAddress((void**)&g_lnv_p, g_lnv);
    float* g_inter_p; cudaGetSymbolAddress((void**)&g_inter_p, g_inter);
    float* g_h_p;     cudaGetSymbolAddress((void**)&g_h_p, g_h);

    int mblk = (n + 127) / 128;

    // CSR build
    zero_cnt_kernel<<<(n + 255) / 256, 256>>>(n);
    hist_kernel<<<(E + 255) / 256, 256>>>(dst, E);
    scan_kernel<<<1, 1024>>>(n);
    scatter_kernel<<<(E + 255) / 256, 256>>>(src, dst, E);

    // projection + attention coefficients
    gemm_kernel<128, 0><<<dim3(mblk, 1), 256>>>(x, fcw, nullptr, nullptr, g_z_p, n);
    eler_kernel<<<(n + 7) / 8, 256>>>(a_l, a_r, n);

    // GAT aggregation + elu + residual + LN
    gat_ln_kernel<<<(n + 7) / 8, 256>>>(x, ln_g, ln_b, n);

    // FFN
    gemm_kernel<128, 1><<<dim3(mblk, 4), 256>>>(g_lnv_p, w1, b1, nullptr, g_inter_p, n);
    gemm_kernel<512, 2><<<dim3(mblk, 1), 256>>>(g_inter_p, w2, b2, g_h_p, (float*)d_out, n);
}

// round 3
// speedup vs baseline: 7.1193x; 1.0034x over previous
#include <cuda_runtime.h>
#include <stdint.h>
#include <math.h>

#define NMAX 50000
#define EMAX 800000

// ---------------- scratch (static __device__ — no allocation) ----------------
__device__ float g_z[(size_t)NMAX * 128];      // per-head projections [N, H*O]
__device__ float g_el[(size_t)NMAX * 8];       // a_l . z  [N,H]
__device__ float g_er[(size_t)NMAX * 8];       // a_r . z  [N,H]
__device__ float g_h[(size_t)NMAX * 128];      // elu(gat)+x  [N,D]
__device__ float g_lnv[(size_t)NMAX * 128];    // layernorm(h)
__device__ float g_inter[(size_t)NMAX * 512];  // gelu(ln@w1+b1)
__device__ int   g_cnt[NMAX];
__device__ int   g_off[NMAX + 1];
__device__ int   g_cur[NMAX];
__device__ int   g_csrc[EMAX];

// ---------------- f32x2 packed-FMA helpers (SASS FFMA2) ----------------
__device__ __forceinline__ unsigned long long pack2(float x) {
    unsigned long long r;
    unsigned xi = __float_as_uint(x);
    asm("mov.b64 %0, {%1, %1};" : "=l"(r) : "r"(xi));
    return r;
}
__device__ __forceinline__ void fma2(unsigned long long& acc,
                                     unsigned long long a, unsigned long long b) {
    asm("fma.rn.f32x2 %0, %1, %2, %0;" : "+l"(acc) : "l"(a), "l"(b));
}
__device__ __forceinline__ float2 unpack2(unsigned long long v) {
    unsigned lo, hi;
    asm("mov.b64 {%0, %1}, %2;" : "=r"(lo), "=r"(hi) : "l"(v));
    return make_float2(__uint_as_float(lo), __uint_as_float(hi));
}
__device__ __forceinline__ float gelu_exact(float v) {
    return 0.5f * v * (1.0f + erff(v * 0.70710678118654752440f));
}

// =====================================================================
// Register-tiled GEMM: C[M,N] = A[M,KTOT] @ B[KTOT,N]
// BM=BN=128, BK=16, 256 threads (16x16), 8x8 outputs per thread
// (split 4+4 rows / 4+4 cols for conflict-free LDS.128).
// EPI: 0 = proj (B gathered from fc_w, out=g_z)
//      1 = ffn1 (gelu(acc+bias) -> g_inter, N=512)
//      2 = ffn2 (acc+bias+res -> out, N=128)
// =====================================================================
template<int KTOT, int EPI>
__global__ __launch_bounds__(256) void gemm_kernel(
    const float* __restrict__ A, const float* __restrict__ B,
    const float* __restrict__ bias, const float* __restrict__ res,
    float* __restrict__ out, int M)
{
    constexpr int NTOT = (EPI == 1) ? 512 : 128;
    __shared__ float As[16 * 132];   // k-major, stride 132 (16B aligned, conflict-spread)
    __shared__ float Bs[16 * 128];   // row-major [k][col]

    const int t  = threadIdx.x;
    const int tx = t & 15, ty = t >> 4;
    const int row0 = blockIdx.x * 128;
    const int col0 = blockIdx.y * 128;

    unsigned long long acc[8][4];
#pragma unroll
    for (int r = 0; r < 8; r++)
#pragma unroll
        for (int p = 0; p < 4; p++) acc[r][p] = 0ull;

    const float4* A4 = (const float4*)A;
    const float4* B4 = (const float4*)B;

#pragma unroll 1
    for (int k0 = 0; k0 < KTOT; k0 += 16) {
        // ---- load A tile [128 rows x 16 k], transposed to As[k][row] ----
#pragma unroll
        for (int i = 0; i < 2; i++) {
            int row = (t >> 2) + i * 64;
            int c4  = t & 3;
            int grow = row0 + row;
            float4 v = make_float4(0.f, 0.f, 0.f, 0.f);
            if (grow < M) v = A4[grow * (KTOT >> 2) + (k0 >> 2) + c4];
            As[(c4 * 4 + 0) * 132 + row] = v.x;
            As[(c4 * 4 + 1) * 132 + row] = v.y;
            As[(c4 * 4 + 2) * 132 + row] = v.z;
            As[(c4 * 4 + 3) * 132 + row] = v.w;
        }
        // ---- load B tile [16 k x 128 cols] ----
        if (EPI == 0) {
            // B[k][n] = fc_w[n>>4][k][n&15], fc_w strides (2048,16,1)
#pragma unroll
            for (int i = 0; i < 8; i++) {
                int idx = t + i * 256;
                int kk = idx >> 7, col = idx & 127;
                Bs[kk * 128 + col] = B[(col >> 4) * 2048 + (k0 + kk) * 16 + (col & 15)];
            }
        } else {
#pragma unroll
            for (int i = 0; i < 2; i++) {
                int kk = t >> 4;
                int c4 = (t & 15) + i * 16;
                float4 v = B4[(size_t)(k0 + kk) * (NTOT >> 2) + (col0 >> 2) + c4];
                ((float4*)Bs)[kk * 32 + c4] = v;
            }
        }
        __syncthreads();

#pragma unroll
        for (int kk = 0; kk < 16; kk++) {
            float4 a0 = *(const float4*)&As[kk * 132 + ty * 4];
            float4 a1 = *(const float4*)&As[kk * 132 + 64 + ty * 4];
            ulonglong2 b0 = *(const ulonglong2*)&Bs[kk * 128 + tx * 4];
            ulonglong2 b1 = *(const ulonglong2*)&Bs[kk * 128 + 64 + tx * 4];
            float av[8] = {a0.x, a0.y, a0.z, a0.w, a1.x, a1.y, a1.z, a1.w};
#pragma unroll
            for (int r = 0; r < 8; r++) {
                unsigned long long pa = pack2(av[r]);
                fma2(acc[r][0], pa, b0.x);
                fma2(acc[r][1], pa, b0.y);
                fma2(acc[r][2], pa, b1.x);
                fma2(acc[r][3], pa, b1.y);
            }
        }
        __syncthreads();
    }

    // ---- epilogue ----
#pragma unroll
    for (int r = 0; r < 8; r++) {
        int row = row0 + ((r < 4) ? (ty * 4 + r) : (64 + ty * 4 + r - 4));
        if (row >= M) continue;
#pragma unroll
        for (int p = 0; p < 4; p++) {
            float2 v = unpack2(acc[r][p]);
            int lcol = (p < 2) ? (tx * 4 + 2 * p) : (64 + tx * 4 + 2 * (p - 2));
            int col = col0 + lcol;
            if (EPI == 0) {
                *(float2*)&out[(size_t)row * 128 + col] = v;
            } else if (EPI == 1) {
                v.x = gelu_exact(v.x + bias[col]);
                v.y = gelu_exact(v.y + bias[col + 1]);
                *(float2*)&out[(size_t)row * 512 + col] = v;
            } else {
                v.x += bias[col] + res[(size_t)row * 128 + col];
                v.y += bias[col + 1] + res[(size_t)row * 128 + col + 1];
                *(float2*)&out[(size_t)row * 128 + col] = v;
            }
        }
    }
}

// =====================================================================
// el/er epilogue: warp per node. lane l covers dims l*4..l*4+3 (head l>>2).
// =====================================================================
__global__ __launch_bounds__(256) void eler_kernel(
    const float* __restrict__ a_l, const float* __restrict__ a_r, int n)
{
    int warp = (blockIdx.x * blockDim.x + threadIdx.x) >> 5;
    int lane = threadIdx.x & 31;
    if (warp >= n) return;
    float4 z = ((const float4*)g_z)[(size_t)warp * 32 + lane];
    float4 al = ((const float4*)a_l)[lane];
    float4 ar = ((const float4*)a_r)[lane];
    float sl = z.x * al.x + z.y * al.y + z.z * al.z + z.w * al.w;
    float sr = z.x * ar.x + z.y * ar.y + z.z * ar.z + z.w * ar.w;
    sl += __shfl_xor_sync(0xffffffffu, sl, 1);
    sl += __shfl_xor_sync(0xffffffffu, sl, 2);
    sr += __shfl_xor_sync(0xffffffffu, sr, 1);
    sr += __shfl_xor_sync(0xffffffffu, sr, 2);
    if ((lane & 3) == 0) {
        int head = lane >> 2;
        g_el[warp * 8 + head] = sl;
        g_er[warp * 8 + head] = sr;
    }
}

// =====================================================================
// CSR build
// =====================================================================
__global__ void zero_cnt_kernel(int n) {
    int i = blockIdx.x * blockDim.x + threadIdx.x;
    if (i < n) g_cnt[i] = 0;
}

__global__ void hist_kernel(const int* __restrict__ dst, int E) {
    int i = blockIdx.x * blockDim.x + threadIdx.x;
    if (i < E) atomicAdd(&g_cnt[dst[i]], 1);
}

__global__ __launch_bounds__(1024) void scan_kernel(int n) {
    int t = threadIdx.x;
    int chunk = (n + 1023) >> 10;
    int b = t * chunk;
    int e = b + chunk; if (e > n) e = n;
    int s = 0;
    for (int i = b; i < e; i++) s += g_cnt[i];
    int own = s;
    int lane = t & 31, w = t >> 5;
#pragma unroll
    for (int d = 1; d < 32; d <<= 1) {
        int v = __shfl_up_sync(0xffffffffu, s, d);
        if (lane >= d) s += v;
    }
    __shared__ int ws[32];
    if (lane == 31) ws[w] = s;
    __syncthreads();
    if (w == 0) {
        int v = ws[lane];
#pragma unroll
        for (int d = 1; d < 32; d <<= 1) {
            int u = __shfl_up_sync(0xffffffffu, v, d);
            if (lane >= d) v += u;
        }
        ws[lane] = v;
    }
    __syncthreads();
    int run = s - own + (w ? ws[w - 1] : 0);
    for (int i = b; i < e; i++) {
        g_off[i] = run;
        g_cur[i] = run;
        run += g_cnt[i];
    }
    if (t == 1023) g_off[n] = ws[31];
}

__global__ void scatter_kernel(const int* __restrict__ src, const int* __restrict__ dst, int E) {
    int i = blockIdx.x * blockDim.x + threadIdx.x;
    if (i < E) {
        int d = dst[i];
        int p = atomicAdd(&g_cur[d], 1);
        g_csrc[p] = src[i];
    }
}

// =====================================================================
// GAT: per-dst softmax + aggregation + elu + residual + fused LayerNorm
// One warp per dst node.
// =====================================================================
__global__ __launch_bounds__(256) void gat_ln_kernel(
    const float* __restrict__ x,
    const float* __restrict__ gg, const float* __restrict__ bb, int n)
{
    int warp = (blockIdx.x * blockDim.x + threadIdx.x) >> 5;
    int lane = threadIdx.x & 31;
    if (warp >= n) return;
    int d = warp;
    int beg = g_off[d], end = g_off[d + 1];

    int h1 = lane & 7, eo = lane >> 3;
    float er_a = g_er[d * 8 + h1];

    // pass 1: per-head denominator (4 edges x 8 heads per step)
    float denom = 0.f;
    int iters = (end - beg + 3) >> 2;
    for (int it = 0; it < iters; it++) {
        int idx = beg + it * 4 + eo;
        float ex = 0.f;
        if (idx < end) {
            int s = g_csrc[idx];
            float e = g_el[s * 8 + h1] + er_a;
            e = (e > 0.f) ? e : 0.01f * e;
            ex = __expf(e);
        }
        denom += ex;
    }
    denom += __shfl_xor_sync(0xffffffffu, denom, 8);
    denom += __shfl_xor_sync(0xffffffffu, denom, 16);

    int h2 = lane >> 2;
    float dh = __shfl_sync(0xffffffffu, denom, h2);
    float er_b = __shfl_sync(0xffffffffu, er_a, h2);
    float rd = (dh > 0.f) ? (1.0f / dh) : 0.f;

    // pass 2: weighted aggregation (lane owns 4 contiguous dims in head h2)
    float4 acc = make_float4(0.f, 0.f, 0.f, 0.f);
    const float4* z4 = (const float4*)g_z;
    for (int i = beg; i < end; i++) {
        int s = g_csrc[i];
        float e = g_el[s * 8 + h2] + er_b;
        e = (e > 0.f) ? e : 0.01f * e;
        float alpha = __expf(e) * rd;
        float4 zv = z4[(size_t)s * 32 + lane];
        acc.x += alpha * zv.x;
        acc.y += alpha * zv.y;
        acc.z += alpha * zv.z;
        acc.w += alpha * zv.w;
    }

    // elu + residual
    float4 xr = ((const float4*)x)[(size_t)d * 32 + lane];
    acc.x = ((acc.x > 0.f) ? acc.x : (__expf(acc.x) - 1.f)) + xr.x;
    acc.y = ((acc.y > 0.f) ? acc.y : (__expf(acc.y) - 1.f)) + xr.y;
    acc.z = ((acc.z > 0.f) ? acc.z : (__expf(acc.z) - 1.f)) + xr.z;
    acc.w = ((acc.w > 0.f) ? acc.w : (__expf(acc.w) - 1.f)) + xr.w;
    ((float4*)g_h)[(size_t)d * 32 + lane] = acc;

    // fused LayerNorm
    float s = acc.x + acc.y + acc.z + acc.w;
#pragma unroll
    for (int o = 16; o; o >>= 1) s += __shfl_xor_sync(0xffffffffu, s, o);
    float mu = s * (1.f / 128.f);
    float dx = acc.x - mu, dy = acc.y - mu, dz = acc.z - mu, dw = acc.w - mu;
    float q = dx * dx + dy * dy + dz * dz + dw * dw;
#pragma unroll
    for (int o = 16; o; o >>= 1) q += __shfl_xor_sync(0xffffffffu, q, o);
    float rs = rsqrtf(q * (1.f / 128.f) + 1e-6f);
    float4 g4 = ((const float4*)gg)[lane];
    float4 b4 = ((const float4*)bb)[lane];
    float4 o4 = make_float4(dx * rs * g4.x + b4.x, dy * rs * g4.y + b4.y,
                            dz * rs * g4.z + b4.z, dw * rs * g4.w + b4.w);
    ((float4*)g_lnv)[(size_t)d * 32 + lane] = o4;
}

// =====================================================================
extern "C" void kernel_launch(void* const* d_in, const int* in_sizes, int n_in,
                              void* d_out, int out_size)
{
    const float* x    = (const float*)d_in[0];
    const float* fcw  = (const float*)d_in[1];
    const float* a_l  = (const float*)d_in[2];
    const float* a_r  = (const float*)d_in[3];
    const float* ln_g = (const float*)d_in[4];
    const float* ln_b = (const float*)d_in[5];
    const float* w1   = (const float*)d_in[6];
    const float* b1   = (const float*)d_in[7];
    const float* w2   = (const float*)d_in[8];
    const float* b2   = (const float*)d_in[9];
    const int*   src  = (const int*)d_in[10];
    const int*   dst  = (const int*)d_in[11];

    int n = in_sizes[0] / 128;
    int E = in_sizes[10];

    float* g_z_p;     cudaGetSymbolAddress((void**)&g_z_p, g_z);
    float* g_lnv_p;   cudaGetSymbolAddress((void**)&g_lnv_p, g_lnv);
    float* g_inter_p; cudaGetSymbolAddress((void**)&g_inter_p, g_inter);
    float* g_h_p;     cudaGetSymbolAddress((void**)&g_h_p, g_h);

    int mblk = (n + 127) / 128;

    // CSR build
    zero_cnt_kernel<<<(n + 255) / 256, 256>>>(n);
    hist_kernel<<<(E + 255) / 256, 256>>>(dst, E);
    scan_kernel<<<1, 1024>>>(n);
    scatter_kernel<<<(E + 255) / 256, 256>>>(src, dst, E);

    // projection + attention coefficients
    gemm_kernel<128, 0><<<dim3(mblk, 1), 256>>>(x, fcw, nullptr, nullptr, g_z_p, n);
    eler_kernel<<<(n + 7) / 8, 256>>>(a_l, a_r, n);

    // GAT aggregation + elu + residual + LN
    gat_ln_kernel<<<(n + 7) / 8, 256>>>(x, ln_g, ln_b, n);

    // FFN
    gemm_kernel<128, 1><<<dim3(mblk, 4), 256>>>(g_lnv_p, w1, b1, nullptr, g_inter_p, n);
    gemm_kernel<512, 2><<<dim3(mblk, 1), 256>>>(g_inter_p, w2, b2, g_h_p, (float*)d_out, n);
}